// round 15
// baseline (speedup 1.0000x reference)
#include <cuda_runtime.h>

#define NUM_NODES 50000
#define C 64
#define NUM_EDGES 800000
#define QUAD_E (NUM_EDGES / 4)

// Scratch (allocation-free rule: __device__ globals)
// Layout: [(NUM_NODES+1)*C aggr incl. trash row][NUM_NODES deg] -> ONE memset.
#define AGGR_FLOATS ((NUM_NODES + 1) * C)
__device__ __align__(16) float g_aggr[AGGR_FLOATS + NUM_NODES];
#define G_DEG (g_aggr + AGGR_FLOATS)
#define TRASH_OFF (NUM_NODES * 256)

__device__ __align__(16) float g_Wt[128 * 64];   // W transposed: [k][o]

// ---------------------------------------------------------------------------
// s2 Kernel: transpose W [o][k] -> g_Wt [k][o]. 32 blocks x 256.
// ---------------------------------------------------------------------------
__global__ void wprep_kernel(const float* __restrict__ W) {
    int i = blockIdx.x * 256 + threadIdx.x;
    if (i < 64 * 128) {
        int o = i >> 7;
        int k = i & 127;
        g_Wt[k * 64 + o] = W[i];
    }
}

// ---------------------------------------------------------------------------
// Kernel: FUSED pack+scatter — 16 lanes per 4-edge group.
// Lanes 0-3 load row indices, 4-7 load col indices; per-block dtype detect
// (int64 view of the row half is in-bounds for both widths); shuffle-
// broadcast byte offsets (-1 = invalid); inline deg atomics; then the
// validated quad gather/RED body (4 x LDG.128 + 4 x RED.128, MLP=4).
// Grid exact: QUAD_E * 16 / 256 = 12500.
// ---------------------------------------------------------------------------
__global__ void scatter_kernel(const float* __restrict__ x,
                               const void* __restrict__ ei_raw) {
    int idx    = blockIdx.x * 256 + threadIdx.x;
    int q      = idx >> 4;        // quad index [0, QUAD_E)
    int lane16 = idx & 15;
    int e_base = q << 2;          // first of this group's 4 edges

    const long long* ei64 = (const long long*)ei_raw;

    // Row half via int64 view (safe read for both widths); block-wide detect.
    long long rv = 0;
    bool pred = true;
    if (lane16 < 4) {
        rv = __ldg(&ei64[e_base + lane16]);
        pred = (rv >= 0 && rv < NUM_NODES);
    }
    int is64 = __syncthreads_and(pred);

    // Per-lane offset contribution: lanes 0-3 -> row byte-offset,
    // lanes 4-7 -> col byte-offset. -1 marks invalid.
    int sv = -1;
    if (is64) {
        if (lane16 < 4) {
            sv = (int)rv << 8;                      // all rows valid when is64
        } else if (lane16 < 8) {
            long long c = __ldg(&ei64[NUM_EDGES + e_base + (lane16 - 4)]);
            sv = (c >= 0 && c < NUM_NODES) ? ((int)c << 8) : -1;
        }
    } else {
        const int* ei32 = (const int*)ei_raw;
        if (lane16 < 4) {
            int r = __ldg(&ei32[e_base + lane16]);
            sv = (r >= 0 && r < NUM_NODES) ? (r << 8) : -1;
        } else if (lane16 < 8) {
            int c = __ldg(&ei32[NUM_EDGES + e_base + (lane16 - 4)]);
            sv = (c >= 0 && c < NUM_NODES) ? (c << 8) : -1;
        }
    }

    // Broadcast all 8 offsets to every lane of the group.
    const unsigned m = 0xFFFFFFFFu;
    int gb = (threadIdx.x & 31) & 16;    // group base within warp: 0 or 16
    int r0 = __shfl_sync(m, sv, gb + 0);
    int r1 = __shfl_sync(m, sv, gb + 1);
    int r2 = __shfl_sync(m, sv, gb + 2);
    int r3 = __shfl_sync(m, sv, gb + 3);
    int c0 = __shfl_sync(m, sv, gb + 4);
    int c1 = __shfl_sync(m, sv, gb + 5);
    int c2 = __shfl_sync(m, sv, gb + 6);
    int c3 = __shfl_sync(m, sv, gb + 7);

    bool ok0 = (r0 | c0) >= 0;   // both non-negative
    bool ok1 = (r1 | c1) >= 0;
    bool ok2 = (r2 | c2) >= 0;
    bool ok3 = (r3 | c3) >= 0;

    // Degree atomics: one lane per edge (lanes 4-7 hold the col index).
    if (lane16 >= 4 && lane16 < 8) {
        bool okj = (lane16 == 4) ? ok0 : (lane16 == 5) ? ok1
                 : (lane16 == 6) ? ok2 : ok3;
        if (okj) atomicAdd(&G_DEG[sv >> 8], 1.0f);
    }

    // Quad gather + RED body (byte-identical to validated R13 layout).
    int chunk = lane16;
    const char* xb = (const char*)x;
    float4 v0 = __ldg((const float4*)(xb + (ok0 ? r0 : 0)) + chunk);
    float4 v1 = __ldg((const float4*)(xb + (ok1 ? r1 : 0)) + chunk);
    float4 v2 = __ldg((const float4*)(xb + (ok2 ? r2 : 0)) + chunk);
    float4 v3 = __ldg((const float4*)(xb + (ok3 ? r3 : 0)) + chunk);

    int cb = chunk << 2;
    char* ab = (char*)g_aggr;
    float* d0 = (float*)(ab + (ok0 ? c0 : TRASH_OFF)) + cb;
    float* d1 = (float*)(ab + (ok1 ? c1 : TRASH_OFF)) + cb;
    float* d2 = (float*)(ab + (ok2 ? c2 : TRASH_OFF)) + cb;
    float* d3 = (float*)(ab + (ok3 ? c3 : TRASH_OFF)) + cb;
    asm volatile("red.global.add.v4.f32 [%0], {%1,%2,%3,%4};"
                 :: "l"(d0), "f"(v0.x), "f"(v0.y), "f"(v0.z), "f"(v0.w) : "memory");
    asm volatile("red.global.add.v4.f32 [%0], {%1,%2,%3,%4};"
                 :: "l"(d1), "f"(v1.x), "f"(v1.y), "f"(v1.z), "f"(v1.w) : "memory");
    asm volatile("red.global.add.v4.f32 [%0], {%1,%2,%3,%4};"
                 :: "l"(d2), "f"(v2.x), "f"(v2.y), "f"(v2.z), "f"(v2.w) : "memory");
    asm volatile("red.global.add.v4.f32 [%0], {%1,%2,%3,%4};"
                 :: "l"(d3), "f"(v3.x), "f"(v3.y), "f"(v3.z), "f"(v3.w) : "memory");
}

// ---------------------------------------------------------------------------
// s2 Kernel: x_gemm — out[n] = x[n] @ W1^T + b   (K = 64, W1 = W[:, :64])
// ---------------------------------------------------------------------------
#define XF_STRIDE 65
#define XG_SMEM ((64 * 64 + 64 * XF_STRIDE) * 4)

__global__ void __launch_bounds__(256)
x_gemm_kernel(const float* __restrict__ x,
              const float* __restrict__ b,
              float* __restrict__ out) {
    extern __shared__ float sm[];
    float* Wt = sm;                 // [k][o] k=0..63, stride 64
    float* F  = sm + 64 * 64;       // [c][n] stride 65

    int t = threadIdx.x;
    int base = blockIdx.x * 64;

    #pragma unroll
    for (int i = t; i < 64 * 64 / 4; i += 256)
        ((float4*)Wt)[i] = ((const float4*)g_Wt)[i];     // rows 0..63

    #pragma unroll
    for (int i = t; i < 64 * 64; i += 256) {
        int nl = i >> 6;
        int c  = i & 63;
        int n  = base + nl;
        F[c * XF_STRIDE + nl] = (n < NUM_NODES) ? x[n * C + c] : 0.f;
    }
    __syncthreads();

    int nl = t & 63;
    int o0 = (t >> 6) << 4;   // 0,16,32,48 (warp-uniform)
    int n  = base + nl;

    unsigned long long acc[8];
    #pragma unroll
    for (int p = 0; p < 8; p++) acc[p] = 0ULL;

    const float* frow = F + nl;
    const float* wrow = Wt + o0;

    #pragma unroll 8
    for (int k = 0; k < 64; k++) {
        float f = frow[k * XF_STRIDE];
        unsigned long long fp;
        asm("mov.b64 %0, {%1, %1};" : "=l"(fp) : "f"(f));
        const ulonglong2* wv = (const ulonglong2*)(wrow + k * 64);
        ulonglong2 w01 = wv[0];
        ulonglong2 w23 = wv[1];
        ulonglong2 w45 = wv[2];
        ulonglong2 w67 = wv[3];
        asm("fma.rn.f32x2 %0, %1, %2, %0;" : "+l"(acc[0]) : "l"(w01.x), "l"(fp));
        asm("fma.rn.f32x2 %0, %1, %2, %0;" : "+l"(acc[1]) : "l"(w01.y), "l"(fp));
        asm("fma.rn.f32x2 %0, %1, %2, %0;" : "+l"(acc[2]) : "l"(w23.x), "l"(fp));
        asm("fma.rn.f32x2 %0, %1, %2, %0;" : "+l"(acc[3]) : "l"(w23.y), "l"(fp));
        asm("fma.rn.f32x2 %0, %1, %2, %0;" : "+l"(acc[4]) : "l"(w45.x), "l"(fp));
        asm("fma.rn.f32x2 %0, %1, %2, %0;" : "+l"(acc[5]) : "l"(w45.y), "l"(fp));
        asm("fma.rn.f32x2 %0, %1, %2, %0;" : "+l"(acc[6]) : "l"(w67.x), "l"(fp));
        asm("fma.rn.f32x2 %0, %1, %2, %0;" : "+l"(acc[7]) : "l"(w67.y), "l"(fp));
    }

    if (n >= NUM_NODES) return;

    float* orow = out + n * C + o0;
    #pragma unroll
    for (int j = 0; j < 4; j++) {
        float lo0, hi0, lo1, hi1;
        asm("mov.b64 {%0, %1}, %2;" : "=f"(lo0), "=f"(hi0) : "l"(acc[2 * j]));
        asm("mov.b64 {%0, %1}, %2;" : "=f"(lo1), "=f"(hi1) : "l"(acc[2 * j + 1]));
        float4 r;
        r.x = lo0 + b[o0 + 4 * j + 0];
        r.y = hi0 + b[o0 + 4 * j + 1];
        r.z = lo1 + b[o0 + 4 * j + 2];
        r.w = hi1 + b[o0 + 4 * j + 3];
        *(float4*)(orow + 4 * j) = r;
    }
}

// ---------------------------------------------------------------------------
// Kernel: aggr_gemm — out[n] += (aggr[n]*rdeg) @ W2^T   (K = 64, W2 = W[:, 64:])
// ---------------------------------------------------------------------------
#define AG_SMEM ((64 * 64 + 64 * XF_STRIDE + 64) * 4)

__global__ void __launch_bounds__(256)
aggr_gemm_kernel(float* __restrict__ out) {
    extern __shared__ float sm[];
    float* Wt   = sm;                          // [k][o] k=64..127
    float* F    = sm + 64 * 64;                // [c][n] stride 65
    float* rdeg = sm + 64 * 64 + 64 * XF_STRIDE;

    int t = threadIdx.x;
    int base = blockIdx.x * 64;

    #pragma unroll
    for (int i = t; i < 64 * 64 / 4; i += 256)
        ((float4*)Wt)[i] = ((const float4*)(g_Wt + 64 * 64))[i];  // rows 64..127

    if (t < 64) {
        int n = base + t;
        rdeg[t] = (n < NUM_NODES) ? __frcp_rn(fmaxf(G_DEG[n], 1.0f)) : 0.0f;
    }
    __syncthreads();

    #pragma unroll
    for (int i = t; i < 64 * 64; i += 256) {
        int nl = i >> 6;
        int c  = i & 63;
        int n  = base + nl;
        F[c * XF_STRIDE + nl] = (n < NUM_NODES) ? g_aggr[n * C + c] * rdeg[nl] : 0.f;
    }
    __syncthreads();

    int nl = t & 63;
    int o0 = (t >> 6) << 4;
    int n  = base + nl;

    unsigned long long acc[8];
    #pragma unroll
    for (int p = 0; p < 8; p++) acc[p] = 0ULL;

    const float* frow = F + nl;
    const float* wrow = Wt + o0;

    #pragma unroll 8
    for (int k = 0; k < 64; k++) {
        float f = frow[k * XF_STRIDE];
        unsigned long long fp;
        asm("mov.b64 %0, {%1, %1};" : "=l"(fp) : "f"(f));
        const ulonglong2* wv = (const ulonglong2*)(wrow + k * 64);
        ulonglong2 w01 = wv[0];
        ulonglong2 w23 = wv[1];
        ulonglong2 w45 = wv[2];
        ulonglong2 w67 = wv[3];
        asm("fma.rn.f32x2 %0, %1, %2, %0;" : "+l"(acc[0]) : "l"(w01.x), "l"(fp));
        asm("fma.rn.f32x2 %0, %1, %2, %0;" : "+l"(acc[1]) : "l"(w01.y), "l"(fp));
        asm("fma.rn.f32x2 %0, %1, %2, %0;" : "+l"(acc[2]) : "l"(w23.x), "l"(fp));
        asm("fma.rn.f32x2 %0, %1, %2, %0;" : "+l"(acc[3]) : "l"(w23.y), "l"(fp));
        asm("fma.rn.f32x2 %0, %1, %2, %0;" : "+l"(acc[4]) : "l"(w45.x), "l"(fp));
        asm("fma.rn.f32x2 %0, %1, %2, %0;" : "+l"(acc[5]) : "l"(w45.y), "l"(fp));
        asm("fma.rn.f32x2 %0, %1, %2, %0;" : "+l"(acc[6]) : "l"(w67.x), "l"(fp));
        asm("fma.rn.f32x2 %0, %1, %2, %0;" : "+l"(acc[7]) : "l"(w67.y), "l"(fp));
    }

    if (n >= NUM_NODES) return;

    float* orow = out + n * C + o0;
    #pragma unroll
    for (int j = 0; j < 4; j++) {
        float lo0, hi0, lo1, hi1;
        asm("mov.b64 {%0, %1}, %2;" : "=f"(lo0), "=f"(hi0) : "l"(acc[2 * j]));
        asm("mov.b64 {%0, %1}, %2;" : "=f"(lo1), "=f"(hi1) : "l"(acc[2 * j + 1]));
        float4 r = *(float4*)(orow + 4 * j);
        r.x += lo0; r.y += hi0; r.z += lo1; r.w += hi1;
        *(float4*)(orow + 4 * j) = r;
    }
}

// ---------------------------------------------------------------------------
extern "C" void kernel_launch(void* const* d_in, const int* in_sizes, int n_in,
                              void* d_out, int out_size) {
    const float* x   = (const float*)d_in[0];
    const void*  ei  = d_in[1];
    const float* W   = (const float*)d_in[2];
    const float* b   = (const float*)d_in[3];
    float*       out = (float*)d_out;

    // Host-side resources created once (no device allocation involved).
    static cudaStream_t s2 = nullptr;
    static cudaEvent_t ev_fork = nullptr, ev_join = nullptr;
    if (s2 == nullptr) {
        cudaStreamCreateWithFlags(&s2, cudaStreamNonBlocking);
        cudaEventCreateWithFlags(&ev_fork, cudaEventDisableTiming);
        cudaEventCreateWithFlags(&ev_join, cudaEventDisableTiming);
    }

    void* aggr_ptr = nullptr;
    cudaGetSymbolAddress(&aggr_ptr, g_aggr);

    // Fork s2 FIRST: wprep -> x_gemm run from t=0, no memset dependency.
    cudaEventRecord(ev_fork, 0);
    cudaStreamWaitEvent(s2, ev_fork, 0);
    wprep_kernel<<<32, 256, 0, s2>>>(W);
    x_gemm_kernel<<<(NUM_NODES + 63) / 64, 256, XG_SMEM, s2>>>(x, b, out);
    cudaEventRecord(ev_join, s2);

    // Main: one memset (aggr + trash row + deg) -> fused pack+scatter.
    cudaMemsetAsync(aggr_ptr, 0, (AGGR_FLOATS + NUM_NODES) * sizeof(float));
    scatter_kernel<<<(QUAD_E * 16) / 256, 256>>>(x, ei);

    // Join: aggr_gemm needs scatter (main) + wprep/x_gemm (s2).
    cudaStreamWaitEvent(0, ev_join, 0);
    aggr_gemm_kernel<<<(NUM_NODES + 63) / 64, 256, AG_SMEM>>>(out);
}

// round 16
// speedup vs baseline: 1.0766x; 1.0766x over previous
#include <cuda_runtime.h>

#define NUM_NODES 50000
#define C 64
#define NUM_EDGES 800000
#define HALF_E (NUM_EDGES / 2)
#define QUAD_E (NUM_EDGES / 4)

// Scratch (allocation-free rule: __device__ globals)
// One extra trash row: invalid edges RED into it harmlessly.
__device__ __align__(16) float g_aggr[(NUM_NODES + 1) * C];
__device__ float g_deg[NUM_NODES];
__device__ __align__(16) float g_Wt[128 * 64];    // W transposed: [k][o]
__device__ __align__(16) int2 g_edges[NUM_EDGES]; // {row*256, col*256} byte offsets

// ---------------------------------------------------------------------------
// s2 Kernel: transpose W [o][k] -> g_Wt [k][o]. 32 blocks x 256.
// ---------------------------------------------------------------------------
__global__ void wprep_kernel(const float* __restrict__ W) {
    int i = blockIdx.x * 256 + threadIdx.x;
    if (i < 64 * 128) {
        int o = i >> 7;
        int k = i & 127;
        g_Wt[k * 64 + o] = W[i];
    }
}

// ---------------------------------------------------------------------------
// Kernel: PACK (vectorized, 2 edges/thread). Per-block dtype detect via
// int64 view of the row half (in-bounds for both widths). Grid 625 x 640.
// ---------------------------------------------------------------------------
__global__ void pack_kernel(const void* __restrict__ ei_raw) {
    int t = blockIdx.x * 640 + threadIdx.x;   // [0, HALF_E)

    const long long* ei64 = (const long long*)ei_raw;
    longlong2 rv = __ldg((const longlong2*)ei64 + t);   // edges 2t, 2t+1 row half
    bool in0 = (rv.x >= 0 && rv.x < NUM_NODES);
    bool in1 = (rv.y >= 0 && rv.y < NUM_NODES);
    int is64 = __syncthreads_and(in0 && in1);

    long long r0, r1, c0, c1;
    if (is64) {
        r0 = rv.x; r1 = rv.y;
        longlong2 cv = __ldg((const longlong2*)(ei64 + NUM_EDGES) + t);
        c0 = cv.x; c1 = cv.y;
    } else {
        const int* ei = (const int*)ei_raw;
        int2 rv32 = __ldg((const int2*)ei + t);
        r0 = rv32.x; r1 = rv32.y;
        int2 cv32 = __ldg((const int2*)(ei + NUM_EDGES) + t);
        c0 = cv32.x; c1 = cv32.y;
    }
    bool ok0 = (r0 >= 0 && r0 < NUM_NODES && c0 >= 0 && c0 < NUM_NODES);
    bool ok1 = (r1 >= 0 && r1 < NUM_NODES && c1 >= 0 && c1 < NUM_NODES);

    int4 pk;
    pk.x = ok0 ? (int)r0 * 256 : 0;
    pk.y = ok0 ? (int)c0 * 256 : NUM_NODES * 256;
    pk.z = ok1 ? (int)r1 * 256 : 0;
    pk.w = ok1 ? (int)c1 * 256 : NUM_NODES * 256;
    ((int4*)g_edges)[t] = pk;

    if (ok0) atomicAdd(&g_deg[(int)c0], 1.0f);
    if (ok1) atomicAdd(&g_deg[(int)c1], 1.0f);
}

// ---------------------------------------------------------------------------
// Kernel: QUAD slim scatter (validated R13 winner) — 16 lanes per 4-edge
// group, 2 broadcast int4 loads, 4 x LDG.128 + 4 x RED.128 (MLP=4).
// Grid exact: QUAD_E * 16 / 256 = 12500. Measured 38.1 us.
// ---------------------------------------------------------------------------
__global__ void scatter_kernel(const float* __restrict__ x) {
    int idx = blockIdx.x * 256 + threadIdx.x;
    int q     = idx >> 4;        // quad index [0, QUAD_E)
    int chunk = idx & 15;

    const int4* eq = (const int4*)g_edges;
    int4 o01 = __ldg(eq + 2 * q);       // edges 4q, 4q+1
    int4 o23 = __ldg(eq + 2 * q + 1);   // edges 4q+2, 4q+3

    float4 v0 = __ldg((const float4*)((const char*)x + o01.x) + chunk);
    float4 v1 = __ldg((const float4*)((const char*)x + o01.z) + chunk);
    float4 v2 = __ldg((const float4*)((const char*)x + o23.x) + chunk);
    float4 v3 = __ldg((const float4*)((const char*)x + o23.z) + chunk);

    float* dst0 = (float*)((char*)g_aggr + o01.y) + (chunk << 2);
    float* dst1 = (float*)((char*)g_aggr + o01.w) + (chunk << 2);
    float* dst2 = (float*)((char*)g_aggr + o23.y) + (chunk << 2);
    float* dst3 = (float*)((char*)g_aggr + o23.w) + (chunk << 2);
    asm volatile("red.global.add.v4.f32 [%0], {%1,%2,%3,%4};"
                 :: "l"(dst0), "f"(v0.x), "f"(v0.y), "f"(v0.z), "f"(v0.w) : "memory");
    asm volatile("red.global.add.v4.f32 [%0], {%1,%2,%3,%4};"
                 :: "l"(dst1), "f"(v1.x), "f"(v1.y), "f"(v1.z), "f"(v1.w) : "memory");
    asm volatile("red.global.add.v4.f32 [%0], {%1,%2,%3,%4};"
                 :: "l"(dst2), "f"(v2.x), "f"(v2.y), "f"(v2.z), "f"(v2.w) : "memory");
    asm volatile("red.global.add.v4.f32 [%0], {%1,%2,%3,%4};"
                 :: "l"(dst3), "f"(v3.x), "f"(v3.y), "f"(v3.z), "f"(v3.w) : "memory");
}

// ---------------------------------------------------------------------------
// s2 Kernel: x_gemm — out[n] = x[n] @ W1^T + b   (K = 64, W1 = W[:, :64])
// (unchanged: fully hidden under pack+scatter)
// ---------------------------------------------------------------------------
#define XF_STRIDE 65
#define XG_SMEM ((64 * 64 + 64 * XF_STRIDE) * 4)

__global__ void __launch_bounds__(256)
x_gemm_kernel(const float* __restrict__ x,
              const float* __restrict__ b,
              float* __restrict__ out) {
    extern __shared__ float sm[];
    float* Wt = sm;                 // [k][o] k=0..63, stride 64
    float* F  = sm + 64 * 64;       // [c][n] stride 65

    int t = threadIdx.x;
    int base = blockIdx.x * 64;

    #pragma unroll
    for (int i = t; i < 64 * 64 / 4; i += 256)
        ((float4*)Wt)[i] = ((const float4*)g_Wt)[i];     // rows 0..63

    #pragma unroll
    for (int i = t; i < 64 * 64; i += 256) {
        int nl = i >> 6;
        int c  = i & 63;
        int n  = base + nl;
        F[c * XF_STRIDE + nl] = (n < NUM_NODES) ? x[n * C + c] : 0.f;
    }
    __syncthreads();

    int nl = t & 63;
    int o0 = (t >> 6) << 4;   // 0,16,32,48 (warp-uniform)
    int n  = base + nl;

    unsigned long long acc[8];
    #pragma unroll
    for (int p = 0; p < 8; p++) acc[p] = 0ULL;

    const float* frow = F + nl;
    const float* wrow = Wt + o0;

    #pragma unroll 8
    for (int k = 0; k < 64; k++) {
        float f = frow[k * XF_STRIDE];
        unsigned long long fp;
        asm("mov.b64 %0, {%1, %1};" : "=l"(fp) : "f"(f));
        const ulonglong2* wv = (const ulonglong2*)(wrow + k * 64);
        ulonglong2 w01 = wv[0];
        ulonglong2 w23 = wv[1];
        ulonglong2 w45 = wv[2];
        ulonglong2 w67 = wv[3];
        asm("fma.rn.f32x2 %0, %1, %2, %0;" : "+l"(acc[0]) : "l"(w01.x), "l"(fp));
        asm("fma.rn.f32x2 %0, %1, %2, %0;" : "+l"(acc[1]) : "l"(w01.y), "l"(fp));
        asm("fma.rn.f32x2 %0, %1, %2, %0;" : "+l"(acc[2]) : "l"(w23.x), "l"(fp));
        asm("fma.rn.f32x2 %0, %1, %2, %0;" : "+l"(acc[3]) : "l"(w23.y), "l"(fp));
        asm("fma.rn.f32x2 %0, %1, %2, %0;" : "+l"(acc[4]) : "l"(w45.x), "l"(fp));
        asm("fma.rn.f32x2 %0, %1, %2, %0;" : "+l"(acc[5]) : "l"(w45.y), "l"(fp));
        asm("fma.rn.f32x2 %0, %1, %2, %0;" : "+l"(acc[6]) : "l"(w67.x), "l"(fp));
        asm("fma.rn.f32x2 %0, %1, %2, %0;" : "+l"(acc[7]) : "l"(w67.y), "l"(fp));
    }

    if (n >= NUM_NODES) return;

    float* orow = out + n * C + o0;
    #pragma unroll
    for (int j = 0; j < 4; j++) {
        float lo0, hi0, lo1, hi1;
        asm("mov.b64 {%0, %1}, %2;" : "=f"(lo0), "=f"(hi0) : "l"(acc[2 * j]));
        asm("mov.b64 {%0, %1}, %2;" : "=f"(lo1), "=f"(hi1) : "l"(acc[2 * j + 1]));
        float4 r;
        r.x = lo0 + b[o0 + 4 * j + 0];
        r.y = hi0 + b[o0 + 4 * j + 1];
        r.z = lo1 + b[o0 + 4 * j + 2];
        r.w = hi1 + b[o0 + 4 * j + 3];
        *(float4*)(orow + 4 * j) = r;
    }
}

// ---------------------------------------------------------------------------
// Kernel: aggr_gemm (RESHAPED) — out[n] += (aggr[n]*rdeg) @ W2^T, K=64.
// 32 nodes x 64 outs per 256-thread block; thread = 1 node x 8 outs
// (4 f32x2 accs). Grid 1563, smem 24.7 KB -> 8 CTAs/SM, 64 warps resident.
// ---------------------------------------------------------------------------
#define AF_STRIDE 33
#define AG_SMEM ((64 * 64 + 64 * AF_STRIDE + 32) * 4)   // 24832 B

__global__ void __launch_bounds__(256)
aggr_gemm_kernel(float* __restrict__ out) {
    extern __shared__ float sm[];
    float* Wt   = sm;                           // [k][o] k=64..127, stride 64
    float* F    = sm + 64 * 64;                 // [c][n] stride 33
    float* rdeg = sm + 64 * 64 + 64 * AF_STRIDE;

    int t = threadIdx.x;
    int base = blockIdx.x * 32;

    #pragma unroll
    for (int i = t; i < 64 * 64 / 4; i += 256)
        ((float4*)Wt)[i] = ((const float4*)(g_Wt + 64 * 64))[i];  // rows 64..127

    if (t < 32) {
        int n = base + t;
        rdeg[t] = (n < NUM_NODES) ? __frcp_rn(fmaxf(g_deg[n], 1.0f)) : 0.0f;
    }
    __syncthreads();

    // Stage features transposed: F[c][n], 32 nodes x 64 channels.
    #pragma unroll
    for (int i = t; i < 32 * 64; i += 256) {
        int nl = i >> 6;
        int c  = i & 63;
        int n  = base + nl;
        F[c * AF_STRIDE + nl] = (n < NUM_NODES) ? g_aggr[n * C + c] * rdeg[nl] : 0.f;
    }
    __syncthreads();

    int nl = t & 31;          // node within block
    int o0 = (t >> 5) << 3;   // output base: 0,8,..,56 (warp-uniform)
    int n  = base + nl;

    unsigned long long acc[4] = {0ULL, 0ULL, 0ULL, 0ULL};

    const float* frow = F + nl;
    const float* wrow = Wt + o0;

    #pragma unroll 8
    for (int k = 0; k < 64; k++) {
        float f = frow[k * AF_STRIDE];
        unsigned long long fp;
        asm("mov.b64 %0, {%1, %1};" : "=l"(fp) : "f"(f));
        const ulonglong2* wv = (const ulonglong2*)(wrow + k * 64);
        ulonglong2 w01 = wv[0];
        ulonglong2 w23 = wv[1];
        asm("fma.rn.f32x2 %0, %1, %2, %0;" : "+l"(acc[0]) : "l"(w01.x), "l"(fp));
        asm("fma.rn.f32x2 %0, %1, %2, %0;" : "+l"(acc[1]) : "l"(w01.y), "l"(fp));
        asm("fma.rn.f32x2 %0, %1, %2, %0;" : "+l"(acc[2]) : "l"(w23.x), "l"(fp));
        asm("fma.rn.f32x2 %0, %1, %2, %0;" : "+l"(acc[3]) : "l"(w23.y), "l"(fp));
    }

    if (n >= NUM_NODES) return;

    float* orow = out + n * C + o0;
    #pragma unroll
    for (int j = 0; j < 2; j++) {
        float lo0, hi0, lo1, hi1;
        asm("mov.b64 {%0, %1}, %2;" : "=f"(lo0), "=f"(hi0) : "l"(acc[2 * j]));
        asm("mov.b64 {%0, %1}, %2;" : "=f"(lo1), "=f"(hi1) : "l"(acc[2 * j + 1]));
        float4 r = *(float4*)(orow + 4 * j);
        r.x += lo0; r.y += hi0; r.z += lo1; r.w += hi1;
        *(float4*)(orow + 4 * j) = r;
    }
}

// ---------------------------------------------------------------------------
extern "C" void kernel_launch(void* const* d_in, const int* in_sizes, int n_in,
                              void* d_out, int out_size) {
    const float* x   = (const float*)d_in[0];
    const void*  ei  = d_in[1];
    const float* W   = (const float*)d_in[2];
    const float* b   = (const float*)d_in[3];
    float*       out = (float*)d_out;

    // Host-side resources created once (no device allocation involved).
    static cudaStream_t s2 = nullptr;
    static cudaEvent_t ev_fork = nullptr, ev_aggr = nullptr, ev_join = nullptr;
    if (s2 == nullptr) {
        cudaStreamCreateWithFlags(&s2, cudaStreamNonBlocking);
        cudaEventCreateWithFlags(&ev_fork, cudaEventDisableTiming);
        cudaEventCreateWithFlags(&ev_aggr, cudaEventDisableTiming);
        cudaEventCreateWithFlags(&ev_join, cudaEventDisableTiming);
    }

    void* aggr_ptr = nullptr;
    void* deg_ptr  = nullptr;
    cudaGetSymbolAddress(&aggr_ptr, g_aggr);
    cudaGetSymbolAddress(&deg_ptr, g_deg);

    // Main: memset(deg) -> pack   (pack needs deg zeroed)
    cudaMemsetAsync(deg_ptr, 0, NUM_NODES * sizeof(float));

    // Fork s2: memset(aggr) -> wprep -> x_gemm, concurrent with pack.
    cudaEventRecord(ev_fork, 0);
    cudaStreamWaitEvent(s2, ev_fork, 0);
    cudaMemsetAsync(aggr_ptr, 0, NUM_NODES * C * sizeof(float), s2);
    cudaEventRecord(ev_aggr, s2);
    wprep_kernel<<<32, 256, 0, s2>>>(W);
    x_gemm_kernel<<<(NUM_NODES + 63) / 64, 256, XG_SMEM, s2>>>(x, b, out);
    cudaEventRecord(ev_join, s2);

    pack_kernel<<<HALF_E / 640, 640>>>(ei);

    // Scatter needs aggr zeroed (s2) + pack (main).
    cudaStreamWaitEvent(0, ev_aggr, 0);
    scatter_kernel<<<(QUAD_E * 16) / 256, 256>>>(x);

    // Join: aggr_gemm needs scatter (main) + wprep/x_gemm (s2).
    cudaStreamWaitEvent(0, ev_join, 0);
    aggr_gemm_kernel<<<(NUM_NODES + 31) / 32, 256, AG_SMEM>>>(out);
}

// round 17
// speedup vs baseline: 1.2427x; 1.1543x over previous
#include <cuda_runtime.h>
#include <cuda_fp16.h>

#define NUM_NODES 50000
#define C 64
#define NUM_EDGES 800000
#define HALF_E (NUM_EDGES / 2)
#define QUAD_E (NUM_EDGES / 4)

// Scratch (allocation-free rule: __device__ globals)
// fp16 feature copy + fp16 accumulator (one trash row for invalid edges).
__device__ __align__(16) __half g_xh[NUM_NODES * C];
__device__ __align__(16) __half g_aggr_h[(NUM_NODES + 1) * C];
__device__ float g_deg[NUM_NODES];
__device__ __align__(16) float g_Wt[128 * 64];    // W transposed: [k][o]
__device__ __align__(16) int2 g_edges[NUM_EDGES]; // {row*128, col*128} byte offsets

#define TRASH_OFF (NUM_NODES * 128)

// ---------------------------------------------------------------------------
// s2 Kernel: convert x (fp32) -> g_xh (fp16). 8 floats per thread.
// Grid 1563 x 256 covers 400000 chunks of 8.
// ---------------------------------------------------------------------------
__global__ void convert_kernel(const float* __restrict__ x) {
    int i = blockIdx.x * 256 + threadIdx.x;
    if (i >= NUM_NODES * C / 8) return;
    const float4* xp = (const float4*)x + 2 * i;
    float4 a = __ldg(xp);
    float4 c = __ldg(xp + 1);
    __half2 h0 = __floats2half2_rn(a.x, a.y);
    __half2 h1 = __floats2half2_rn(a.z, a.w);
    __half2 h2 = __floats2half2_rn(c.x, c.y);
    __half2 h3 = __floats2half2_rn(c.z, c.w);
    uint4 o;
    o.x = *(unsigned*)&h0; o.y = *(unsigned*)&h1;
    o.z = *(unsigned*)&h2; o.w = *(unsigned*)&h3;
    ((uint4*)g_xh)[i] = o;
}

// ---------------------------------------------------------------------------
// s2 Kernel: transpose W [o][k] -> g_Wt [k][o]. 32 blocks x 256.
// ---------------------------------------------------------------------------
__global__ void wprep_kernel(const float* __restrict__ W) {
    int i = blockIdx.x * 256 + threadIdx.x;
    if (i < 64 * 128) {
        int o = i >> 7;
        int k = i & 127;
        g_Wt[k * 64 + o] = W[i];
    }
}

// ---------------------------------------------------------------------------
// Kernel: PACK (vectorized, 2 edges/thread). Per-block dtype detect via
// int64 view of the row half (in-bounds for both widths). Grid 625 x 640.
// Offsets are byte offsets into the fp16 arrays (row = 128 B).
// ---------------------------------------------------------------------------
__global__ void pack_kernel(const void* __restrict__ ei_raw) {
    int t = blockIdx.x * 640 + threadIdx.x;   // [0, HALF_E)

    const long long* ei64 = (const long long*)ei_raw;
    longlong2 rv = __ldg((const longlong2*)ei64 + t);   // edges 2t, 2t+1 row half
    bool in0 = (rv.x >= 0 && rv.x < NUM_NODES);
    bool in1 = (rv.y >= 0 && rv.y < NUM_NODES);
    int is64 = __syncthreads_and(in0 && in1);

    long long r0, r1, c0, c1;
    if (is64) {
        r0 = rv.x; r1 = rv.y;
        longlong2 cv = __ldg((const longlong2*)(ei64 + NUM_EDGES) + t);
        c0 = cv.x; c1 = cv.y;
    } else {
        const int* ei = (const int*)ei_raw;
        int2 rv32 = __ldg((const int2*)ei + t);
        r0 = rv32.x; r1 = rv32.y;
        int2 cv32 = __ldg((const int2*)(ei + NUM_EDGES) + t);
        c0 = cv32.x; c1 = cv32.y;
    }
    bool ok0 = (r0 >= 0 && r0 < NUM_NODES && c0 >= 0 && c0 < NUM_NODES);
    bool ok1 = (r1 >= 0 && r1 < NUM_NODES && c1 >= 0 && c1 < NUM_NODES);

    int4 pk;
    pk.x = ok0 ? (int)r0 * 128 : 0;
    pk.y = ok0 ? (int)c0 * 128 : TRASH_OFF;
    pk.z = ok1 ? (int)r1 * 128 : 0;
    pk.w = ok1 ? (int)c1 * 128 : TRASH_OFF;
    ((int4*)g_edges)[t] = pk;

    if (ok0) atomicAdd(&g_deg[(int)c0], 1.0f);
    if (ok1) atomicAdd(&g_deg[(int)c1], 1.0f);
}

// ---------------------------------------------------------------------------
// Kernel: QUAD fp16 scatter — 8 lanes per 4-edge group (row = 128 B),
// 2 broadcast int4 loads, 4 x LDG.128 (8 fp16 each) +
// 4 x red.global.add.noftz.v4.f16x2 (MLP=4). Half the bytes of fp32.
// Grid exact: QUAD_E * 8 / 256 = 6250.
// ---------------------------------------------------------------------------
__global__ void scatter_kernel() {
    int idx = blockIdx.x * 256 + threadIdx.x;
    int q     = idx >> 3;        // quad index [0, QUAD_E)
    int chunk = idx & 7;         // 16B chunk of the 128B row

    const int4* eq = (const int4*)g_edges;
    int4 o01 = __ldg(eq + 2 * q);       // edges 4q, 4q+1
    int4 o23 = __ldg(eq + 2 * q + 1);   // edges 4q+2, 4q+3

    const char* xb = (const char*)g_xh;
    uint4 v0 = __ldg((const uint4*)(xb + o01.x) + chunk);
    uint4 v1 = __ldg((const uint4*)(xb + o01.z) + chunk);
    uint4 v2 = __ldg((const uint4*)(xb + o23.x) + chunk);
    uint4 v3 = __ldg((const uint4*)(xb + o23.z) + chunk);

    int cb = chunk << 4;
    char* ab = (char*)g_aggr_h;
    char* d0 = ab + o01.y + cb;
    char* d1 = ab + o01.w + cb;
    char* d2 = ab + o23.y + cb;
    char* d3 = ab + o23.w + cb;
    asm volatile("red.global.add.noftz.v4.f16x2 [%0], {%1,%2,%3,%4};"
                 :: "l"(d0), "r"(v0.x), "r"(v0.y), "r"(v0.z), "r"(v0.w) : "memory");
    asm volatile("red.global.add.noftz.v4.f16x2 [%0], {%1,%2,%3,%4};"
                 :: "l"(d1), "r"(v1.x), "r"(v1.y), "r"(v1.z), "r"(v1.w) : "memory");
    asm volatile("red.global.add.noftz.v4.f16x2 [%0], {%1,%2,%3,%4};"
                 :: "l"(d2), "r"(v2.x), "r"(v2.y), "r"(v2.z), "r"(v2.w) : "memory");
    asm volatile("red.global.add.noftz.v4.f16x2 [%0], {%1,%2,%3,%4};"
                 :: "l"(d3), "r"(v3.x), "r"(v3.y), "r"(v3.z), "r"(v3.w) : "memory");
}

// ---------------------------------------------------------------------------
// s2 Kernel: x_gemm — out[n] = x[n] @ W1^T + b   (K=64, fp32, unchanged)
// ---------------------------------------------------------------------------
#define XF_STRIDE 65
#define XG_SMEM ((64 * 64 + 64 * XF_STRIDE) * 4)

__global__ void __launch_bounds__(256)
x_gemm_kernel(const float* __restrict__ x,
              const float* __restrict__ b,
              float* __restrict__ out) {
    extern __shared__ float sm[];
    float* Wt = sm;                 // [k][o] k=0..63, stride 64
    float* F  = sm + 64 * 64;       // [c][n] stride 65

    int t = threadIdx.x;
    int base = blockIdx.x * 64;

    #pragma unroll
    for (int i = t; i < 64 * 64 / 4; i += 256)
        ((float4*)Wt)[i] = ((const float4*)g_Wt)[i];     // rows 0..63

    #pragma unroll
    for (int i = t; i < 64 * 64; i += 256) {
        int nl = i >> 6;
        int c  = i & 63;
        int n  = base + nl;
        F[c * XF_STRIDE + nl] = (n < NUM_NODES) ? x[n * C + c] : 0.f;
    }
    __syncthreads();

    int nl = t & 63;
    int o0 = (t >> 6) << 4;   // 0,16,32,48 (warp-uniform)
    int n  = base + nl;

    unsigned long long acc[8];
    #pragma unroll
    for (int p = 0; p < 8; p++) acc[p] = 0ULL;

    const float* frow = F + nl;
    const float* wrow = Wt + o0;

    #pragma unroll 8
    for (int k = 0; k < 64; k++) {
        float f = frow[k * XF_STRIDE];
        unsigned long long fp;
        asm("mov.b64 %0, {%1, %1};" : "=l"(fp) : "f"(f));
        const ulonglong2* wv = (const ulonglong2*)(wrow + k * 64);
        ulonglong2 w01 = wv[0];
        ulonglong2 w23 = wv[1];
        ulonglong2 w45 = wv[2];
        ulonglong2 w67 = wv[3];
        asm("fma.rn.f32x2 %0, %1, %2, %0;" : "+l"(acc[0]) : "l"(w01.x), "l"(fp));
        asm("fma.rn.f32x2 %0, %1, %2, %0;" : "+l"(acc[1]) : "l"(w01.y), "l"(fp));
        asm("fma.rn.f32x2 %0, %1, %2, %0;" : "+l"(acc[2]) : "l"(w23.x), "l"(fp));
        asm("fma.rn.f32x2 %0, %1, %2, %0;" : "+l"(acc[3]) : "l"(w23.y), "l"(fp));
        asm("fma.rn.f32x2 %0, %1, %2, %0;" : "+l"(acc[4]) : "l"(w45.x), "l"(fp));
        asm("fma.rn.f32x2 %0, %1, %2, %0;" : "+l"(acc[5]) : "l"(w45.y), "l"(fp));
        asm("fma.rn.f32x2 %0, %1, %2, %0;" : "+l"(acc[6]) : "l"(w67.x), "l"(fp));
        asm("fma.rn.f32x2 %0, %1, %2, %0;" : "+l"(acc[7]) : "l"(w67.y), "l"(fp));
    }

    if (n >= NUM_NODES) return;

    float* orow = out + n * C + o0;
    #pragma unroll
    for (int j = 0; j < 4; j++) {
        float lo0, hi0, lo1, hi1;
        asm("mov.b64 {%0, %1}, %2;" : "=f"(lo0), "=f"(hi0) : "l"(acc[2 * j]));
        asm("mov.b64 {%0, %1}, %2;" : "=f"(lo1), "=f"(hi1) : "l"(acc[2 * j + 1]));
        float4 r;
        r.x = lo0 + b[o0 + 4 * j + 0];
        r.y = hi0 + b[o0 + 4 * j + 1];
        r.z = lo1 + b[o0 + 4 * j + 2];
        r.w = hi1 + b[o0 + 4 * j + 3];
        *(float4*)(orow + 4 * j) = r;
    }
}

// ---------------------------------------------------------------------------
// Kernel: aggr_gemm — out[n] += (aggr_h[n]*rdeg) @ W2^T, K=64.
// 32 nodes x 64 outs per 256-thread block (R16 shape); fp16 aggr loads
// converted to fp32 during staging.
// ---------------------------------------------------------------------------
#define AF_STRIDE 33
#define AG_SMEM ((64 * 64 + 64 * AF_STRIDE + 32) * 4)

__global__ void __launch_bounds__(256)
aggr_gemm_kernel(float* __restrict__ out) {
    extern __shared__ float sm[];
    float* Wt   = sm;                           // [k][o] k=64..127, stride 64
    float* F    = sm + 64 * 64;                 // [c][n] stride 33
    float* rdeg = sm + 64 * 64 + 64 * AF_STRIDE;

    int t = threadIdx.x;
    int base = blockIdx.x * 32;

    #pragma unroll
    for (int i = t; i < 64 * 64 / 4; i += 256)
        ((float4*)Wt)[i] = ((const float4*)(g_Wt + 64 * 64))[i];  // rows 64..127

    if (t < 32) {
        int n = base + t;
        rdeg[t] = (n < NUM_NODES) ? __frcp_rn(fmaxf(g_deg[n], 1.0f)) : 0.0f;
    }
    __syncthreads();

    // Stage fp16 aggr -> fp32 F[c][n], half2 loads.
    const __half2* ah = (const __half2*)g_aggr_h;
    #pragma unroll
    for (int i = t; i < 32 * 32; i += 256) {
        int nl = i >> 5;
        int c2 = i & 31;        // half2 index: channels 2*c2, 2*c2+1
        int n  = base + nl;
        float2 f = make_float2(0.f, 0.f);
        if (n < NUM_NODES) f = __half22float2(ah[n * 32 + c2]);
        float r = rdeg[nl];
        F[(2 * c2) * AF_STRIDE + nl]     = f.x * r;
        F[(2 * c2 + 1) * AF_STRIDE + nl] = f.y * r;
    }
    __syncthreads();

    int nl = t & 31;          // node within block
    int o0 = (t >> 5) << 3;   // output base: 0,8,..,56 (warp-uniform)
    int n  = base + nl;

    unsigned long long acc[4] = {0ULL, 0ULL, 0ULL, 0ULL};

    const float* frow = F + nl;
    const float* wrow = Wt + o0;

    #pragma unroll 8
    for (int k = 0; k < 64; k++) {
        float f = frow[k * AF_STRIDE];
        unsigned long long fp;
        asm("mov.b64 %0, {%1, %1};" : "=l"(fp) : "f"(f));
        const ulonglong2* wv = (const ulonglong2*)(wrow + k * 64);
        ulonglong2 w01 = wv[0];
        ulonglong2 w23 = wv[1];
        asm("fma.rn.f32x2 %0, %1, %2, %0;" : "+l"(acc[0]) : "l"(w01.x), "l"(fp));
        asm("fma.rn.f32x2 %0, %1, %2, %0;" : "+l"(acc[1]) : "l"(w01.y), "l"(fp));
        asm("fma.rn.f32x2 %0, %1, %2, %0;" : "+l"(acc[2]) : "l"(w23.x), "l"(fp));
        asm("fma.rn.f32x2 %0, %1, %2, %0;" : "+l"(acc[3]) : "l"(w23.y), "l"(fp));
    }

    if (n >= NUM_NODES) return;

    float* orow = out + n * C + o0;
    #pragma unroll
    for (int j = 0; j < 2; j++) {
        float lo0, hi0, lo1, hi1;
        asm("mov.b64 {%0, %1}, %2;" : "=f"(lo0), "=f"(hi0) : "l"(acc[2 * j]));
        asm("mov.b64 {%0, %1}, %2;" : "=f"(lo1), "=f"(hi1) : "l"(acc[2 * j + 1]));
        float4 r = *(float4*)(orow + 4 * j);
        r.x += lo0; r.y += hi0; r.z += lo1; r.w += hi1;
        *(float4*)(orow + 4 * j) = r;
    }
}

// ---------------------------------------------------------------------------
extern "C" void kernel_launch(void* const* d_in, const int* in_sizes, int n_in,
                              void* d_out, int out_size) {
    const float* x   = (const float*)d_in[0];
    const void*  ei  = d_in[1];
    const float* W   = (const float*)d_in[2];
    const float* b   = (const float*)d_in[3];
    float*       out = (float*)d_out;

    // Host-side resources created once (no device allocation involved).
    static cudaStream_t s2 = nullptr;
    static cudaEvent_t ev_fork = nullptr, ev_aggr = nullptr, ev_join = nullptr;
    if (s2 == nullptr) {
        cudaStreamCreateWithFlags(&s2, cudaStreamNonBlocking);
        cudaEventCreateWithFlags(&ev_fork, cudaEventDisableTiming);
        cudaEventCreateWithFlags(&ev_aggr, cudaEventDisableTiming);
        cudaEventCreateWithFlags(&ev_join, cudaEventDisableTiming);
    }

    void* aggr_ptr = nullptr;
    void* deg_ptr  = nullptr;
    cudaGetSymbolAddress(&aggr_ptr, g_aggr_h);
    cudaGetSymbolAddress(&deg_ptr, g_deg);

    // Main: memset(deg) -> pack   (pack needs deg zeroed)
    cudaMemsetAsync(deg_ptr, 0, NUM_NODES * sizeof(float));

    // Fork s2: memset(aggr_h) + convert (scatter deps), then wprep -> x_gemm.
    cudaEventRecord(ev_fork, 0);
    cudaStreamWaitEvent(s2, ev_fork, 0);
    cudaMemsetAsync(aggr_ptr, 0, (NUM_NODES + 1) * C * sizeof(__half), s2);
    convert_kernel<<<(NUM_NODES * C / 8 + 255) / 256, 256, 0, s2>>>(x);
    cudaEventRecord(ev_aggr, s2);
    wprep_kernel<<<32, 256, 0, s2>>>(W);
    x_gemm_kernel<<<(NUM_NODES + 63) / 64, 256, XG_SMEM, s2>>>(x, b, out);
    cudaEventRecord(ev_join, s2);

    pack_kernel<<<HALF_E / 640, 640>>>(ei);

    // Scatter needs aggr_h zeroed + xh (s2) + pack (main).
    cudaStreamWaitEvent(0, ev_aggr, 0);
    scatter_kernel<<<(QUAD_E * 8) / 256, 256>>>();

    // Join: aggr_gemm needs scatter (main) + wprep/x_gemm (s2).
    cudaStreamWaitEvent(0, ev_join, 0);
    aggr_gemm_kernel<<<(NUM_NODES + 31) / 32, 256, AG_SMEM>>>(out);
}